// round 2
// baseline (speedup 1.0000x reference)
#include <cuda_runtime.h>
#include <cuda_bf16.h>
#include <math.h>

// ---------------- problem constants ----------------
#define BQ 2
#define LQ 2048
#define MROWS (BQ * LQ)     // 4096
#define DQ 256
#define SQ 8
#define DEPTHQ 4
#define DSQ (DQ + SQ)       // 264
#define VOCABQ 32000

// ---------------- scratch (no allocations allowed) ----------------
__device__ float g_hA[MROWS * DQ];
__device__ float g_hB[MROWS * DQ];
__device__ float g_comb[MROWS * DSQ];
__device__ float g_gate[MROWS * SQ];
__device__ float g_hn[MROWS * DQ];

// ---------------- embed gather ----------------
__global__ void embed_kernel(const int* __restrict__ x_t,
                             const float* __restrict__ table,
                             float* __restrict__ h) {
    int i = blockIdx.x * blockDim.x + threadIdx.x;   // over MROWS*DQ
    if (i >= MROWS * DQ) return;
    int row = i >> 8;
    int d = i & 255;
    h[i] = table[(size_t)x_t[row] * DQ + d];
}

// ---------------- generic SGEMM: C = A(MxK) * B(KxN) + bias ----------------
// A row-major, B row-major. M % 128 == 0 assumed (always 4096 here).
// N % 4 == 0 assumed (264/256/32000). K arbitrary.
#define BM 128
#define BN 128
#define BKS 16
#define TM 8
#define TN 8

__global__ __launch_bounds__(256)
void sgemm_bias(const float* __restrict__ A, const float* __restrict__ B,
                const float* __restrict__ bias, float* __restrict__ C,
                int M, int N, int K) {
    __shared__ float As[BKS][BM];
    __shared__ float Bs[BKS][BN];

    const int tid = threadIdx.x;
    const int brow = blockIdx.y;
    const int bcol = blockIdx.x;
    const int tx = tid & 15;         // 0..15  -> N direction
    const int ty = tid >> 4;         // 0..15  -> M direction

    float acc[TM][TN];
#pragma unroll
    for (int i = 0; i < TM; i++)
#pragma unroll
        for (int j = 0; j < TN; j++) acc[i][j] = 0.f;

    for (int kt = 0; kt < K; kt += BKS) {
        // load A tile (BM x BKS): 512 float4 slots, 2 per thread
#pragma unroll
        for (int it = 0; it < 2; it++) {
            int id = tid + it * 256;
            int ar = id >> 2;            // 0..127
            int ac = (id & 3) << 2;      // 0,4,8,12
            float4 v = make_float4(0.f, 0.f, 0.f, 0.f);
            if (kt + ac < K) {           // K % 4 == 0 always
                v = *(const float4*)(A + (size_t)(brow * BM + ar) * K + kt + ac);
            }
            As[ac + 0][ar] = v.x;
            As[ac + 1][ar] = v.y;
            As[ac + 2][ar] = v.z;
            As[ac + 3][ar] = v.w;
        }
        // load B tile (BKS x BN): 512 float4 slots, 2 per thread
#pragma unroll
        for (int it = 0; it < 2; it++) {
            int id = tid + it * 256;
            int br = id >> 5;            // 0..15
            int bc = (id & 31) << 2;     // 0..124
            int gcol = bcol * BN + bc;
            float4 v = make_float4(0.f, 0.f, 0.f, 0.f);
            if ((kt + br < K) && (gcol < N)) {
                v = *(const float4*)(B + (size_t)(kt + br) * N + gcol);
            }
            *(float4*)&Bs[br][bc] = v;
        }
        __syncthreads();

#pragma unroll
        for (int k = 0; k < BKS; k++) {
            float ra[TM], rb[TN];
#pragma unroll
            for (int i = 0; i < TM; i++) ra[i] = As[k][ty * TM + i];
#pragma unroll
            for (int j = 0; j < TN; j++) rb[j] = Bs[k][tx * TN + j];
#pragma unroll
            for (int i = 0; i < TM; i++)
#pragma unroll
                for (int j = 0; j < TN; j++) acc[i][j] += ra[i] * rb[j];
        }
        __syncthreads();
    }

    // epilogue
    const int colbase = bcol * BN + tx * TN;
#pragma unroll
    for (int i = 0; i < TM; i++) {
        size_t row = (size_t)(brow * BM + ty * TM + i);
        float* Crow = C + row * (size_t)N + colbase;
#pragma unroll
        for (int j = 0; j < TN; j += 4) {
            if (colbase + j < N) {
                float4 o;
                o.x = acc[i][j + 0] + __ldg(bias + colbase + j + 0);
                o.y = acc[i][j + 1] + __ldg(bias + colbase + j + 1);
                o.z = acc[i][j + 2] + __ldg(bias + colbase + j + 2);
                o.w = acc[i][j + 3] + __ldg(bias + colbase + j + 3);
                *(float4*)(Crow + j) = o;
            }
        }
    }
}

// ---------------- gate = sigmoid(combined @ Wg + bg) ----------------
__global__ __launch_bounds__(256)
void gate_kernel(const float* __restrict__ combined,
                 const float* __restrict__ Wg,
                 const float* __restrict__ bg,
                 float* __restrict__ gate) {
    __shared__ float sWg[DSQ * SQ];   // 2112 floats
    for (int j = threadIdx.x; j < DSQ * SQ; j += blockDim.x) sWg[j] = Wg[j];
    __syncthreads();

    int i = blockIdx.x * blockDim.x + threadIdx.x;   // over MROWS*SQ
    if (i >= MROWS * SQ) return;
    int row = i >> 3;
    int s = i & 7;
    const float* c = combined + (size_t)row * DSQ;
    float acc = bg[s];
#pragma unroll 8
    for (int e = 0; e < DSQ; e++) acc += c[e] * sWg[e * SQ + s];
    gate[i] = 1.f / (1.f + expf(-acc));
}

// ---------------- sequential scan over L, in-place into combined[:,256:264] ----
__global__ void scan_kernel(const float* __restrict__ gate,
                            float* __restrict__ combined,
                            float* __restrict__ out_states) {
    int t = threadIdx.x;
    if (t >= BQ * SQ) return;
    int b = t >> 3;
    int s = t & 7;
    float state = 0.f;
    for (int l0 = 0; l0 < LQ; l0 += 8) {
        float g[8], si[8];
#pragma unroll
        for (int u = 0; u < 8; u++) {
            int idx = b * LQ + l0 + u;
            g[u]  = gate[idx * SQ + s];
            si[u] = combined[(size_t)idx * DSQ + DQ + s];
        }
#pragma unroll
        for (int u = 0; u < 8; u++) {
            int idx = b * LQ + l0 + u;
            state = g[u] * state + (1.f - g[u]) * si[u];
            combined[(size_t)idx * DSQ + DQ + s] = state;
        }
    }
    out_states[b * SQ + s] = state;
}

// ---------------- layernorm (one warp per row, D=256) ----------------
__global__ __launch_bounds__(256)
void layernorm_kernel(const float* __restrict__ x,
                      const float* __restrict__ gamma,
                      const float* __restrict__ beta,
                      float* __restrict__ y) {
    int warp = (blockIdx.x * blockDim.x + threadIdx.x) >> 5;
    int lane = threadIdx.x & 31;
    if (warp >= MROWS) return;
    const float* xr = x + (size_t)warp * DQ;
    float v[8];
    float sum = 0.f;
#pragma unroll
    for (int i = 0; i < 8; i++) { v[i] = xr[lane + i * 32]; sum += v[i]; }
#pragma unroll
    for (int o = 16; o; o >>= 1) sum += __shfl_xor_sync(0xFFFFFFFFu, sum, o);
    float mu = sum * (1.f / 256.f);
    float vs = 0.f;
#pragma unroll
    for (int i = 0; i < 8; i++) { float d = v[i] - mu; vs += d * d; }
#pragma unroll
    for (int o = 16; o; o >>= 1) vs += __shfl_xor_sync(0xFFFFFFFFu, vs, o);
    float r = rsqrtf(vs * (1.f / 256.f) + 1e-5f);
    float* yr = y + (size_t)warp * DQ;
#pragma unroll
    for (int i = 0; i < 8; i++) {
        int d = lane + i * 32;
        yr[d] = (v[i] - mu) * r * gamma[d] + beta[d];
    }
}

// ---------------- launch ----------------
extern "C" void kernel_launch(void* const* d_in, const int* in_sizes, int n_in,
                              void* d_out, int out_size) {
    const int*   x_t   = (const int*)  d_in[0];
    const float* table = (const float*)d_in[1];
    const float* Wi    = (const float*)d_in[2];
    const float* bi    = (const float*)d_in[3];
    const float* Wg    = (const float*)d_in[4];
    const float* bg    = (const float*)d_in[5];
    const float* Wo    = (const float*)d_in[6];
    const float* bo    = (const float*)d_in[7];
    const float* gamma = (const float*)d_in[8];
    const float* beta  = (const float*)d_in[9];
    const float* Wc    = (const float*)d_in[10];
    const float* bc    = (const float*)d_in[11];
    const float* Wr    = (const float*)d_in[12];
    const float* br    = (const float*)d_in[13];

    float* out = (float*)d_out;
    const size_t logits_elems = (size_t)MROWS * VOCABQ;        // 131072000
    const size_t recon_elems  = (size_t)MROWS * DQ;            // 1048576
    float* logits  = out;
    float* recon   = out + logits_elems;
    float* ostates = out + logits_elems + recon_elems;         // DEPTH*B*S = 64

    float *hA, *hB, *comb, *gatep, *hn;
    cudaGetSymbolAddress((void**)&hA,    g_hA);
    cudaGetSymbolAddress((void**)&hB,    g_hB);
    cudaGetSymbolAddress((void**)&comb,  g_comb);
    cudaGetSymbolAddress((void**)&gatep, g_gate);
    cudaGetSymbolAddress((void**)&hn,    g_hn);

    // 1) embed
    embed_kernel<<<(MROWS * DQ + 255) / 256, 256>>>(x_t, table, hA);

    // 2) layers
    float* cur = hA;
    float* nxt = hB;
    for (int layer = 0; layer < DEPTHQ; layer++) {
        // combined = cur @ Wi[layer] + bi[layer]   (4096x256 @ 256x264)
        {
            dim3 grid((DSQ + BN - 1) / BN, MROWS / BM);
            sgemm_bias<<<grid, 256>>>(cur, Wi + (size_t)layer * DQ * DSQ,
                                      bi + (size_t)layer * DSQ, comb,
                                      MROWS, DSQ, DQ);
        }
        // gate
        gate_kernel<<<(MROWS * SQ + 255) / 256, 256>>>(
            comb, Wg + (size_t)layer * DSQ * SQ, bg + (size_t)layer * SQ, gatep);
        // scan (overwrites state_in slots with states; writes final states)
        scan_kernel<<<1, 32>>>(gatep, comb, ostates + layer * BQ * SQ);
        // nxt = [embed_part, states] @ Wo[layer] + bo[layer]  (4096x264 @ 264x256)
        {
            dim3 grid((DQ + BN - 1) / BN, MROWS / BM);
            sgemm_bias<<<grid, 256>>>(comb, Wo + (size_t)layer * DSQ * DQ,
                                      bo + (size_t)layer * DQ, nxt,
                                      MROWS, DQ, DSQ);
        }
        float* t = cur; cur = nxt; nxt = t;
    }

    // 3) layernorm
    layernorm_kernel<<<(MROWS * 32 + 255) / 256, 256>>>(cur, gamma, beta, hn);

    // 4) logits = hn @ Wc + bc    (4096x256 @ 256x32000)
    {
        dim3 grid(VOCABQ / BN, MROWS / BM);   // 250 x 32
        sgemm_bias<<<grid, 256>>>(hn, Wc, bc, logits, MROWS, VOCABQ, DQ);
    }
    // 5) recon = hn @ Wr + br     (4096x256 @ 256x256)
    {
        dim3 grid(DQ / BN, MROWS / BM);       // 2 x 32
        sgemm_bias<<<grid, 256>>>(hn, Wr, br, recon, MROWS, DQ, DQ);
    }
}

// round 3
// speedup vs baseline: 1.1254x; 1.1254x over previous
#include <cuda_runtime.h>
#include <cuda_bf16.h>
#include <math.h>

// ---------------- problem constants ----------------
#define BQ 2
#define LQ 2048
#define MROWS (BQ * LQ)     // 4096
#define DQ 256
#define SQ 8
#define DEPTHQ 4
#define DSQ (DQ + SQ)       // 264
#define VOCABQ 32000

// ---------------- scratch (no allocations allowed) ----------------
__device__ float g_hA[MROWS * DQ];
__device__ float g_hB[MROWS * DQ];
__device__ float g_comb[MROWS * DSQ];
__device__ float g_gate[MROWS * SQ];
__device__ float g_hn[MROWS * DQ];

// ---------------- embed gather ----------------
__global__ void embed_kernel(const int* __restrict__ x_t,
                             const float* __restrict__ table,
                             float* __restrict__ h) {
    int i = blockIdx.x * blockDim.x + threadIdx.x;   // over MROWS*DQ
    if (i >= MROWS * DQ) return;
    int row = i >> 8;
    int d = i & 255;
    h[i] = table[(size_t)x_t[row] * DQ + d];
}

// ---------------- generic SGEMM: C = A(MxK) * B(KxN) + bias ----------------
// A row-major, B row-major. M % 128 == 0 (always 4096 here). N % 8 == 0.
// Register-prefetch double buffering: next tiles load into regs during compute.
#define BM 128
#define BN 128
#define BKS 16
#define TM 8
#define TN 8

__global__ __launch_bounds__(256)
void sgemm_bias(const float* __restrict__ A, const float* __restrict__ B,
                const float* __restrict__ bias, float* __restrict__ C,
                int M, int N, int K) {
    __shared__ float As[BKS][BM];
    __shared__ float Bs[BKS][BN];

    const int tid = threadIdx.x;
    const int brow = blockIdx.y;
    const int bcol = blockIdx.x;
    const int tx = tid & 15;         // 0..15  -> N direction
    const int ty = tid >> 4;         // 0..15  -> M direction

    // per-thread load coordinates (2 float4 each for A and B)
    const int a_r0 = tid >> 2;                 // 0..63
    const int a_c  = (tid & 3) << 2;           // 0,4,8,12
    const int b_r0 = tid >> 5;                 // 0..7
    const int b_c  = (tid & 31) << 2;          // 0..124
    const int gcol = bcol * BN + b_c;

    float acc[TM][TN];
#pragma unroll
    for (int i = 0; i < TM; i++)
#pragma unroll
        for (int j = 0; j < TN; j++) acc[i][j] = 0.f;

    // ---- load tile 0 directly to smem ----
    {
        const int kt = 0;
#pragma unroll
        for (int it = 0; it < 2; it++) {
            int ar = a_r0 + it * 64;
            float4 v = make_float4(0.f, 0.f, 0.f, 0.f);
            if (kt + a_c < K)
                v = *(const float4*)(A + (size_t)(brow * BM + ar) * K + kt + a_c);
            As[a_c + 0][ar] = v.x; As[a_c + 1][ar] = v.y;
            As[a_c + 2][ar] = v.z; As[a_c + 3][ar] = v.w;
        }
#pragma unroll
        for (int it = 0; it < 2; it++) {
            int br = b_r0 + it * 8;
            float4 v = make_float4(0.f, 0.f, 0.f, 0.f);
            if ((kt + br < K) && (gcol < N))
                v = *(const float4*)(B + (size_t)(kt + br) * N + gcol);
            *(float4*)&Bs[br][b_c] = v;
        }
    }
    __syncthreads();

    for (int kt = 0; kt < K; kt += BKS) {
        const int ktn = kt + BKS;
        const bool havenext = ktn < K;
        float4 pa[2], pb[2];
        if (havenext) {
#pragma unroll
            for (int it = 0; it < 2; it++) {
                int ar = a_r0 + it * 64;
                pa[it] = make_float4(0.f, 0.f, 0.f, 0.f);
                if (ktn + a_c < K)
                    pa[it] = *(const float4*)(A + (size_t)(brow * BM + ar) * K + ktn + a_c);
            }
#pragma unroll
            for (int it = 0; it < 2; it++) {
                int br = b_r0 + it * 8;
                pb[it] = make_float4(0.f, 0.f, 0.f, 0.f);
                if ((ktn + br < K) && (gcol < N))
                    pb[it] = *(const float4*)(B + (size_t)(ktn + br) * N + gcol);
            }
        }

#pragma unroll
        for (int k = 0; k < BKS; k++) {
            float ra[TM], rb[TN];
#pragma unroll
            for (int i = 0; i < TM; i++) ra[i] = As[k][ty * TM + i];
#pragma unroll
            for (int j = 0; j < TN; j++) rb[j] = Bs[k][tx * TN + j];
#pragma unroll
            for (int i = 0; i < TM; i++)
#pragma unroll
                for (int j = 0; j < TN; j++) acc[i][j] += ra[i] * rb[j];
        }

        if (havenext) {
            __syncthreads();
#pragma unroll
            for (int it = 0; it < 2; it++) {
                int ar = a_r0 + it * 64;
                As[a_c + 0][ar] = pa[it].x; As[a_c + 1][ar] = pa[it].y;
                As[a_c + 2][ar] = pa[it].z; As[a_c + 3][ar] = pa[it].w;
            }
#pragma unroll
            for (int it = 0; it < 2; it++) {
                int br = b_r0 + it * 8;
                *(float4*)&Bs[br][b_c] = pb[it];
            }
            __syncthreads();
        }
    }

    // epilogue
    const int colbase = bcol * BN + tx * TN;
#pragma unroll
    for (int i = 0; i < TM; i++) {
        size_t row = (size_t)(brow * BM + ty * TM + i);
        float* Crow = C + row * (size_t)N + colbase;
#pragma unroll
        for (int j = 0; j < TN; j += 4) {
            if (colbase + j < N) {
                float4 o;
                o.x = acc[i][j + 0] + __ldg(bias + colbase + j + 0);
                o.y = acc[i][j + 1] + __ldg(bias + colbase + j + 1);
                o.z = acc[i][j + 2] + __ldg(bias + colbase + j + 2);
                o.w = acc[i][j + 3] + __ldg(bias + colbase + j + 3);
                *(float4*)(Crow + j) = o;
            }
        }
    }
}

// ---------------- gate = sigmoid(combined @ Wg + bg) ----------------
__global__ __launch_bounds__(256)
void gate_kernel(const float* __restrict__ combined,
                 const float* __restrict__ Wg,
                 const float* __restrict__ bg,
                 float* __restrict__ gate) {
    __shared__ float sWg[DSQ * SQ];   // 2112 floats
    for (int j = threadIdx.x; j < DSQ * SQ; j += blockDim.x) sWg[j] = Wg[j];
    __syncthreads();

    int i = blockIdx.x * blockDim.x + threadIdx.x;   // over MROWS*SQ
    if (i >= MROWS * SQ) return;
    int row = i >> 3;
    int s = i & 7;
    const float* c = combined + (size_t)row * DSQ;
    float acc = bg[s];
#pragma unroll 8
    for (int e = 0; e < DSQ; e++) acc += c[e] * sWg[e * SQ + s];
    gate[i] = 1.f / (1.f + expf(-acc));
}

// ---------------- parallel scan over L (affine-map composition) ----------
// 16 blocks: one per (b,s) chain. 256 threads x 8 steps each.
// f(x) = g*x + (1-g)*s_in;  (a2,b2)o(a1,b1) = (a2*a1, a2*b1 + b2).
#define SCAN_T 256
#define SCAN_STEPS (LQ / SCAN_T)   // 8

__global__ __launch_bounds__(SCAN_T)
void scan_kernel(const float* __restrict__ gate,
                 float* __restrict__ combined,
                 float* __restrict__ out_states) {
    const int b = blockIdx.x >> 3;
    const int s = blockIdx.x & 7;
    const int t = threadIdx.x;
    const int l0 = t * SCAN_STEPS;

    float g[SCAN_STEPS], si[SCAN_STEPS];
#pragma unroll
    for (int u = 0; u < SCAN_STEPS; u++) {
        int idx = b * LQ + l0 + u;
        g[u]  = gate[idx * SQ + s];
        si[u] = combined[(size_t)idx * DSQ + DQ + s];
    }

    // local composite over 8 steps
    float a = 1.f, bb = 0.f;
#pragma unroll
    for (int u = 0; u < SCAN_STEPS; u++) {
        a  = g[u] * a;
        bb = g[u] * bb + (1.f - g[u]) * si[u];
    }

    __shared__ float sa[SCAN_T], sb[SCAN_T];
    sa[t] = a; sb[t] = bb;
    __syncthreads();

    // Hillis-Steele inclusive scan of affine composites
#pragma unroll
    for (int off = 1; off < SCAN_T; off <<= 1) {
        float pa = 1.f, pb = 0.f, ca = sa[t], cb = sb[t];
        if (t >= off) { pa = sa[t - off]; pb = sb[t - off]; }
        __syncthreads();
        if (t >= off) {
            sa[t] = ca * pa;
            sb[t] = ca * pb + cb;
        }
        __syncthreads();
    }

    // state entering this thread's segment = prefix(t-1) applied to 0
    float st = (t == 0) ? 0.f : sb[t - 1];

#pragma unroll
    for (int u = 0; u < SCAN_STEPS; u++) {
        int idx = b * LQ + l0 + u;
        st = g[u] * st + (1.f - g[u]) * si[u];
        combined[(size_t)idx * DSQ + DQ + s] = st;
    }
    if (t == SCAN_T - 1) out_states[b * SQ + s] = st;
}

// ---------------- layernorm (one warp per row, D=256) ----------------
__global__ __launch_bounds__(256)
void layernorm_kernel(const float* __restrict__ x,
                      const float* __restrict__ gamma,
                      const float* __restrict__ beta,
                      float* __restrict__ y) {
    int warp = (blockIdx.x * blockDim.x + threadIdx.x) >> 5;
    int lane = threadIdx.x & 31;
    if (warp >= MROWS) return;
    const float* xr = x + (size_t)warp * DQ;
    float v[8];
    float sum = 0.f;
#pragma unroll
    for (int i = 0; i < 8; i++) { v[i] = xr[lane + i * 32]; sum += v[i]; }
#pragma unroll
    for (int o = 16; o; o >>= 1) sum += __shfl_xor_sync(0xFFFFFFFFu, sum, o);
    float mu = sum * (1.f / 256.f);
    float vs = 0.f;
#pragma unroll
    for (int i = 0; i < 8; i++) { float d = v[i] - mu; vs += d * d; }
#pragma unroll
    for (int o = 16; o; o >>= 1) vs += __shfl_xor_sync(0xFFFFFFFFu, vs, o);
    float r = rsqrtf(vs * (1.f / 256.f) + 1e-5f);
    float* yr = y + (size_t)warp * DQ;
#pragma unroll
    for (int i = 0; i < 8; i++) {
        int d = lane + i * 32;
        yr[d] = (v[i] - mu) * r * gamma[d] + beta[d];
    }
}

// ---------------- launch ----------------
extern "C" void kernel_launch(void* const* d_in, const int* in_sizes, int n_in,
                              void* d_out, int out_size) {
    const int*   x_t   = (const int*)  d_in[0];
    const float* table = (const float*)d_in[1];
    const float* Wi    = (const float*)d_in[2];
    const float* bi    = (const float*)d_in[3];
    const float* Wg    = (const float*)d_in[4];
    const float* bg    = (const float*)d_in[5];
    const float* Wo    = (const float*)d_in[6];
    const float* bo    = (const float*)d_in[7];
    const float* gamma = (const float*)d_in[8];
    const float* beta  = (const float*)d_in[9];
    const float* Wc    = (const float*)d_in[10];
    const float* bc    = (const float*)d_in[11];
    const float* Wr    = (const float*)d_in[12];
    const float* br    = (const float*)d_in[13];

    float* out = (float*)d_out;
    const size_t logits_elems = (size_t)MROWS * VOCABQ;        // 131072000
    const size_t recon_elems  = (size_t)MROWS * DQ;            // 1048576
    float* logits  = out;
    float* recon   = out + logits_elems;
    float* ostates = out + logits_elems + recon_elems;         // DEPTH*B*S = 64

    float *hA, *hB, *comb, *gatep, *hn;
    cudaGetSymbolAddress((void**)&hA,    g_hA);
    cudaGetSymbolAddress((void**)&hB,    g_hB);
    cudaGetSymbolAddress((void**)&comb,  g_comb);
    cudaGetSymbolAddress((void**)&gatep, g_gate);
    cudaGetSymbolAddress((void**)&hn,    g_hn);

    // 1) embed
    embed_kernel<<<(MROWS * DQ + 255) / 256, 256>>>(x_t, table, hA);

    // 2) layers
    float* cur = hA;
    float* nxt = hB;
    for (int layer = 0; layer < DEPTHQ; layer++) {
        // combined = cur @ Wi[layer] + bi[layer]   (4096x256 @ 256x264)
        {
            dim3 grid((DSQ + BN - 1) / BN, MROWS / BM);
            sgemm_bias<<<grid, 256>>>(cur, Wi + (size_t)layer * DQ * DSQ,
                                      bi + (size_t)layer * DSQ, comb,
                                      MROWS, DSQ, DQ);
        }
        // gate
        gate_kernel<<<(MROWS * SQ + 255) / 256, 256>>>(
            comb, Wg + (size_t)layer * DSQ * SQ, bg + (size_t)layer * SQ, gatep);
        // parallel scan (overwrites state_in slots with states; writes finals)
        scan_kernel<<<BQ * SQ, SCAN_T>>>(gatep, comb, ostates + layer * BQ * SQ);
        // nxt = [embed_part, states] @ Wo[layer] + bo[layer]  (4096x264 @ 264x256)
        {
            dim3 grid((DQ + BN - 1) / BN, MROWS / BM);
            sgemm_bias<<<grid, 256>>>(comb, Wo + (size_t)layer * DSQ * DQ,
                                      bo + (size_t)layer * DQ, nxt,
                                      MROWS, DQ, DSQ);
        }
        float* t = cur; cur = nxt; nxt = t;
    }

    // 3) layernorm
    layernorm_kernel<<<(MROWS * 32 + 255) / 256, 256>>>(cur, gamma, beta, hn);

    // 4) logits = hn @ Wc + bc    (4096x256 @ 256x32000)
    {
        dim3 grid(VOCABQ / BN, MROWS / BM);   // 250 x 32
        sgemm_bias<<<grid, 256>>>(hn, Wc, bc, logits, MROWS, VOCABQ, DQ);
    }
    // 5) recon = hn @ Wr + br     (4096x256 @ 256x256)
    {
        dim3 grid(DQ / BN, MROWS / BM);       // 2 x 32
        sgemm_bias<<<grid, 256>>>(hn, Wr, br, recon, MROWS, DQ, DQ);
    }
}

// round 5
// speedup vs baseline: 2.1643x; 1.9232x over previous
#include <cuda_runtime.h>
#include <cuda_fp16.h>
#include <math.h>
#include <stdint.h>

// ---------------- problem constants ----------------
#define BQ 2
#define LQ 2048
#define MROWS (BQ * LQ)     // 4096
#define DQ 256
#define SQ 8
#define DEPTHQ 4
#define DSQ (DQ + SQ)       // 264
#define VOCABQ 32000

// ---------------- scratch (no allocations allowed) ----------------
__device__ float g_hA[MROWS * DQ];
__device__ float g_hB[MROWS * DQ];
__device__ float g_comb[MROWS * DSQ];
__device__ float g_gate[MROWS * SQ];
__device__ float g_hn[MROWS * DQ];
// fp16 operands for tensor-core logits GEMM
__device__ __half g_Af[MROWS * DQ];        // hn as fp16, [M][K]
__device__ __half g_Bt[VOCABQ * DQ];       // Wc transposed, [N][K]

// ================= PTX helpers (base sm_103 ISA only) =================
__device__ __forceinline__ uint32_t smem_u32(const void* p) {
    uint32_t a;
    asm("{ .reg .u64 t; cvta.to.shared.u64 t, %1; cvt.u32.u64 %0, t; }" : "=r"(a) : "l"(p));
    return a;
}
__device__ __forceinline__ void cpa16(uint32_t dst, const void* src) {
    asm volatile("cp.async.cg.shared.global [%0], [%1], 16;" :: "r"(dst), "l"(src));
}
__device__ __forceinline__ void cpa_commit() { asm volatile("cp.async.commit_group;" ::: "memory"); }
__device__ __forceinline__ void cpa_wait1()  { asm volatile("cp.async.wait_group 1;" ::: "memory"); }
__device__ __forceinline__ void cpa_wait0()  { asm volatile("cp.async.wait_group 0;" ::: "memory"); }

__device__ __forceinline__ void ldmx4(uint32_t* r, uint32_t addr) {
    asm volatile("ldmatrix.sync.aligned.m8n8.x4.shared.b16 {%0,%1,%2,%3}, [%4];"
                 : "=r"(r[0]), "=r"(r[1]), "=r"(r[2]), "=r"(r[3]) : "r"(addr));
}
__device__ __forceinline__ void mma16816(float* d, const uint32_t* a, uint32_t b0, uint32_t b1) {
    asm volatile(
        "mma.sync.aligned.m16n8k16.row.col.f32.f16.f16.f32 "
        "{%0,%1,%2,%3}, {%4,%5,%6,%7}, {%8,%9}, {%0,%1,%2,%3};"
        : "+f"(d[0]), "+f"(d[1]), "+f"(d[2]), "+f"(d[3])
        : "r"(a[0]), "r"(a[1]), "r"(a[2]), "r"(a[3]), "r"(b0), "r"(b1));
}

// ================= fp16 tensor-core logits GEMM =================
// C[M=4096, N=32000] = A[M][K=256] * Bt[N][K]^T + bias
// CTA tile 128x128, 8 warps in 2(M) x 4(N), warp tile 64x32, K-chunk 32.
#define TCM 128
#define TCN 128
#define TCK 32
#define HPAD 40   // fp16 per smem row (80 B) -> conflict-free ldmatrix

__global__ __launch_bounds__(256)
void hgemm_logits(const __half* __restrict__ A, const __half* __restrict__ Bt,
                  const float* __restrict__ bias, float* __restrict__ C) {
    __shared__ __half As[2][TCM * HPAD];
    __shared__ __half Bs[2][TCN * HPAD];

    const int tid = threadIdx.x;
    const int wid = tid >> 5, lane = tid & 31;
    const int wm = wid & 1, wn = wid >> 1;      // warp coords: 2 x 4
    const int m0 = blockIdx.y * TCM;
    const int n0 = blockIdx.x * TCN;

    float acc[4][4][4];
#pragma unroll
    for (int i = 0; i < 4; i++)
#pragma unroll
        for (int j = 0; j < 4; j++)
#pragma unroll
            for (int q = 0; q < 4; q++) acc[i][j][q] = 0.f;

    // per-thread load slots: 1024 chunks of 16B (A 512 + B 512), 4 per thread
    // A chunk idx i<512: r=i>>2 (row 0..127), c=i&3 (16B col)
    const uint32_t asb[2] = { smem_u32(As[0]), smem_u32(As[1]) };
    const uint32_t bsb[2] = { smem_u32(Bs[0]), smem_u32(Bs[1]) };

    auto load_stage = [&](int s, int k0) {
#pragma unroll
        for (int it = 0; it < 2; it++) {
            int i = tid + it * 256;            // 0..511 -> A
            int r = i >> 2, c = i & 3;
            cpa16(asb[s] + r * 80 + c * 16, A + (size_t)(m0 + r) * DQ + k0 + c * 8);
        }
#pragma unroll
        for (int it = 0; it < 2; it++) {
            int i = tid + it * 256;            // 0..511 -> B
            int r = i >> 2, c = i & 3;
            cpa16(bsb[s] + r * 80 + c * 16, Bt + (size_t)(n0 + r) * DQ + k0 + c * 8);
        }
        cpa_commit();
    };

    load_stage(0, 0);

    const int lrow = lane & 15;                 // ldmatrix source row
    const int lchunkhalf = lane >> 4;           // 0/1 -> +8 fp16

    for (int kt = 0; kt < DQ / TCK; kt++) {     // 8 iterations
        const int cur = kt & 1;
        if (kt < DQ / TCK - 1) { load_stage(cur ^ 1, (kt + 1) * TCK); cpa_wait1(); }
        else                   { cpa_wait0(); }
        __syncthreads();

#pragma unroll
        for (int ks = 0; ks < 2; ks++) {        // two k16 steps in the 32-chunk
            const int chunk = ks * 2 + lchunkhalf;   // 16B col within row
            uint32_t af[4][4], bf[2][4];
#pragma unroll
            for (int mi = 0; mi < 4; mi++) {
                int r = wm * 64 + mi * 16 + lrow;
                ldmx4(af[mi], asb[cur] + r * 80 + chunk * 16);
            }
#pragma unroll
            for (int bj = 0; bj < 2; bj++) {
                int r = wn * 32 + bj * 16 + lrow;
                ldmx4(bf[bj], bsb[cur] + r * 80 + chunk * 16);
            }
#pragma unroll
            for (int mi = 0; mi < 4; mi++)
#pragma unroll
                for (int nj = 0; nj < 4; nj++) {
                    int bj = nj >> 1, hi = nj & 1;
                    mma16816(acc[mi][nj], af[mi], bf[bj][hi], bf[bj][hi + 2]);
                }
        }
        __syncthreads();
    }

    // epilogue
    const int g = lane >> 2, tig = lane & 3;
#pragma unroll
    for (int mi = 0; mi < 4; mi++) {
#pragma unroll
        for (int nj = 0; nj < 4; nj++) {
            int col = n0 + wn * 32 + nj * 8 + 2 * tig;
            float bx = __ldg(bias + col), by = __ldg(bias + col + 1);
            int row0 = m0 + wm * 64 + mi * 16 + g;
            float2 v0 = make_float2(acc[mi][nj][0] + bx, acc[mi][nj][1] + by);
            float2 v1 = make_float2(acc[mi][nj][2] + bx, acc[mi][nj][3] + by);
            *(float2*)(C + (size_t)row0 * VOCABQ + col) = v0;
            *(float2*)(C + (size_t)(row0 + 8) * VOCABQ + col) = v1;
        }
    }
}

// ================= conversion kernels =================
__global__ void to_half_kernel(const float* __restrict__ x, __half* __restrict__ y, int n) {
    int i = blockIdx.x * blockDim.x + threadIdx.x;
    if (i < n) y[i] = __float2half_rn(x[i]);
}

// Wc [K=256][N=32000] -> Bt [N][K] fp16, 32x32 smem tiles
__global__ __launch_bounds__(256)
void transpose_wc_kernel(const float* __restrict__ Wc, __half* __restrict__ Bt) {
    __shared__ float t[32][33];
    const int n0 = blockIdx.x * 32;
    const int k0 = blockIdx.y * 32;
    const int tx = threadIdx.x, ty = threadIdx.y;   // 32 x 8
#pragma unroll
    for (int r = 0; r < 4; r++)
        t[ty * 4 + r][tx] = Wc[(size_t)(k0 + ty * 4 + r) * VOCABQ + n0 + tx];
    __syncthreads();
#pragma unroll
    for (int r = 0; r < 4; r++) {
        int n = n0 + ty * 4 + r;
        Bt[(size_t)n * DQ + k0 + tx] = __float2half_rn(t[tx][ty * 4 + r]);
    }
}

// ---------------- embed gather ----------------
__global__ void embed_kernel(const int* __restrict__ x_t,
                             const float* __restrict__ table,
                             float* __restrict__ h) {
    int i = blockIdx.x * blockDim.x + threadIdx.x;
    if (i >= MROWS * DQ) return;
    int row = i >> 8;
    int d = i & 255;
    h[i] = table[(size_t)x_t[row] * DQ + d];
}

// ---------------- fp32 SGEMM (for small layer GEMMs) ----------------
#define BM 128
#define BN 128
#define BKS 16
#define TM 8
#define TN 8

__global__ __launch_bounds__(256)
void sgemm_bias(const float* __restrict__ A, const float* __restrict__ B,
                const float* __restrict__ bias, float* __restrict__ C,
                int M, int N, int K) {
    __shared__ float As[BKS][BM];
    __shared__ float Bs[BKS][BN];

    const int tid = threadIdx.x;
    const int brow = blockIdx.y;
    const int bcol = blockIdx.x;
    const int tx = tid & 15;
    const int ty = tid >> 4;

    float acc[TM][TN];
#pragma unroll
    for (int i = 0; i < TM; i++)
#pragma unroll
        for (int j = 0; j < TN; j++) acc[i][j] = 0.f;

    for (int kt = 0; kt < K; kt += BKS) {
#pragma unroll
        for (int it = 0; it < 2; it++) {
            int id = tid + it * 256;
            int ar = id >> 2;
            int ac = (id & 3) << 2;
            float4 v = make_float4(0.f, 0.f, 0.f, 0.f);
            if (kt + ac < K)
                v = *(const float4*)(A + (size_t)(brow * BM + ar) * K + kt + ac);
            As[ac + 0][ar] = v.x; As[ac + 1][ar] = v.y;
            As[ac + 2][ar] = v.z; As[ac + 3][ar] = v.w;
        }
#pragma unroll
        for (int it = 0; it < 2; it++) {
            int id = tid + it * 256;
            int br = id >> 5;
            int bc2 = (id & 31) << 2;
            int gcol = bcol * BN + bc2;
            float4 v = make_float4(0.f, 0.f, 0.f, 0.f);
            if ((kt + br < K) && (gcol < N))
                v = *(const float4*)(B + (size_t)(kt + br) * N + gcol);
            *(float4*)&Bs[br][bc2] = v;
        }
        __syncthreads();

#pragma unroll
        for (int k = 0; k < BKS; k++) {
            float ra[TM], rb[TN];
#pragma unroll
            for (int i = 0; i < TM; i++) ra[i] = As[k][ty * TM + i];
#pragma unroll
            for (int j = 0; j < TN; j++) rb[j] = Bs[k][tx * TN + j];
#pragma unroll
            for (int i = 0; i < TM; i++)
#pragma unroll
                for (int j = 0; j < TN; j++) acc[i][j] += ra[i] * rb[j];
        }
        __syncthreads();
    }

    const int colbase = bcol * BN + tx * TN;
#pragma unroll
    for (int i = 0; i < TM; i++) {
        size_t row = (size_t)(brow * BM + ty * TM + i);
        float* Crow = C + row * (size_t)N + colbase;
#pragma unroll
        for (int j = 0; j < TN; j += 4) {
            if (colbase + j < N) {
                float4 o;
                o.x = acc[i][j + 0] + __ldg(bias + colbase + j + 0);
                o.y = acc[i][j + 1] + __ldg(bias + colbase + j + 1);
                o.z = acc[i][j + 2] + __ldg(bias + colbase + j + 2);
                o.w = acc[i][j + 3] + __ldg(bias + colbase + j + 3);
                *(float4*)(Crow + j) = o;
            }
        }
    }
}

// ---------------- gate = sigmoid(combined @ Wg + bg) ----------------
__global__ __launch_bounds__(256)
void gate_kernel(const float* __restrict__ combined,
                 const float* __restrict__ Wg,
                 const float* __restrict__ bg,
                 float* __restrict__ gate) {
    __shared__ float sWg[DSQ * SQ];
    for (int j = threadIdx.x; j < DSQ * SQ; j += blockDim.x) sWg[j] = Wg[j];
    __syncthreads();

    int i = blockIdx.x * blockDim.x + threadIdx.x;
    if (i >= MROWS * SQ) return;
    int row = i >> 3;
    int s = i & 7;
    const float* c = combined + (size_t)row * DSQ;
    float acc = bg[s];
#pragma unroll 8
    for (int e = 0; e < DSQ; e++) acc += c[e] * sWg[e * SQ + s];
    gate[i] = 1.f / (1.f + expf(-acc));
}

// ---------------- parallel scan over L (affine-map composition) ----------
#define SCAN_T 256
#define SCAN_STEPS (LQ / SCAN_T)   // 8

__global__ __launch_bounds__(SCAN_T)
void scan_kernel(const float* __restrict__ gate,
                 float* __restrict__ combined,
                 float* __restrict__ out_states) {
    const int b = blockIdx.x >> 3;
    const int s = blockIdx.x & 7;
    const int t = threadIdx.x;
    const int l0 = t * SCAN_STEPS;

    float g[SCAN_STEPS], si[SCAN_STEPS];
#pragma unroll
    for (int u = 0; u < SCAN_STEPS; u++) {
        int idx = b * LQ + l0 + u;
        g[u]  = gate[idx * SQ + s];
        si[u] = combined[(size_t)idx * DSQ + DQ + s];
    }

    float a = 1.f, bb = 0.f;
#pragma unroll
    for (int u = 0; u < SCAN_STEPS; u++) {
        a  = g[u] * a;
        bb = g[u] * bb + (1.f - g[u]) * si[u];
    }

    __shared__ float sa[SCAN_T], sbv[SCAN_T];
    sa[t] = a; sbv[t] = bb;
    __syncthreads();

#pragma unroll
    for (int off = 1; off < SCAN_T; off <<= 1) {
        float pa = 1.f, pb = 0.f, ca = sa[t], cb = sbv[t];
        if (t >= off) { pa = sa[t - off]; pb = sbv[t - off]; }
        __syncthreads();
        if (t >= off) {
            sa[t] = ca * pa;
            sbv[t] = ca * pb + cb;
        }
        __syncthreads();
    }

    float st = (t == 0) ? 0.f : sbv[t - 1];
#pragma unroll
    for (int u = 0; u < SCAN_STEPS; u++) {
        int idx = b * LQ + l0 + u;
        st = g[u] * st + (1.f - g[u]) * si[u];
        combined[(size_t)idx * DSQ + DQ + s] = st;
    }
    if (t == SCAN_T - 1) out_states[b * SQ + s] = st;
}

// ---------------- layernorm (one warp per row, D=256) ----------------
__global__ __launch_bounds__(256)
void layernorm_kernel(const float* __restrict__ x,
                      const float* __restrict__ gamma,
                      const float* __restrict__ beta,
                      float* __restrict__ y) {
    int warp = (blockIdx.x * blockDim.x + threadIdx.x) >> 5;
    int lane = threadIdx.x & 31;
    if (warp >= MROWS) return;
    const float* xr = x + (size_t)warp * DQ;
    float v[8];
    float sum = 0.f;
#pragma unroll
    for (int i = 0; i < 8; i++) { v[i] = xr[lane + i * 32]; sum += v[i]; }
#pragma unroll
    for (int o = 16; o; o >>= 1) sum += __shfl_xor_sync(0xFFFFFFFFu, sum, o);
    float mu = sum * (1.f / 256.f);
    float vs = 0.f;
#pragma unroll
    for (int i = 0; i < 8; i++) { float d = v[i] - mu; vs += d * d; }
#pragma unroll
    for (int o = 16; o; o >>= 1) vs += __shfl_xor_sync(0xFFFFFFFFu, vs, o);
    float r = rsqrtf(vs * (1.f / 256.f) + 1e-5f);
    float* yr = y + (size_t)warp * DQ;
#pragma unroll
    for (int i = 0; i < 8; i++) {
        int d = lane + i * 32;
        yr[d] = (v[i] - mu) * r * gamma[d] + beta[d];
    }
}

// ---------------- launch ----------------
extern "C" void kernel_launch(void* const* d_in, const int* in_sizes, int n_in,
                              void* d_out, int out_size) {
    const int*   x_t   = (const int*)  d_in[0];
    const float* table = (const float*)d_in[1];
    const float* Wi    = (const float*)d_in[2];
    const float* bi    = (const float*)d_in[3];
    const float* Wg    = (const float*)d_in[4];
    const float* bg    = (const float*)d_in[5];
    const float* Wo    = (const float*)d_in[6];
    const float* bo    = (const float*)d_in[7];
    const float* gamma = (const float*)d_in[8];
    const float* beta  = (const float*)d_in[9];
    const float* Wc    = (const float*)d_in[10];
    const float* bc    = (const float*)d_in[11];
    const float* Wr    = (const float*)d_in[12];
    const float* br    = (const float*)d_in[13];

    float* out = (float*)d_out;
    const size_t logits_elems = (size_t)MROWS * VOCABQ;
    const size_t recon_elems  = (size_t)MROWS * DQ;
    float* logits  = out;
    float* recon   = out + logits_elems;
    float* ostates = out + logits_elems + recon_elems;

    float *hA, *hB, *comb, *gatep, *hn;
    __half *Af, *Bt;
    cudaGetSymbolAddress((void**)&hA,    g_hA);
    cudaGetSymbolAddress((void**)&hB,    g_hB);
    cudaGetSymbolAddress((void**)&comb,  g_comb);
    cudaGetSymbolAddress((void**)&gatep, g_gate);
    cudaGetSymbolAddress((void**)&hn,    g_hn);
    cudaGetSymbolAddress((void**)&Af,    g_Af);
    cudaGetSymbolAddress((void**)&Bt,    g_Bt);

    // Wc transpose to fp16 (independent; launch first to overlap nothing-critical)
    {
        dim3 grid(VOCABQ / 32, DQ / 32);
        transpose_wc_kernel<<<grid, dim3(32, 8)>>>(Wc, Bt);
    }

    // 1) embed
    embed_kernel<<<(MROWS * DQ + 255) / 256, 256>>>(x_t, table, hA);

    // 2) layers (fp32)
    float* cur = hA;
    float* nxt = hB;
    for (int layer = 0; layer < DEPTHQ; layer++) {
        {
            dim3 grid((DSQ + BN - 1) / BN, MROWS / BM);
            sgemm_bias<<<grid, 256>>>(cur, Wi + (size_t)layer * DQ * DSQ,
                                      bi + (size_t)layer * DSQ, comb,
                                      MROWS, DSQ, DQ);
        }
        gate_kernel<<<(MROWS * SQ + 255) / 256, 256>>>(
            comb, Wg + (size_t)layer * DSQ * SQ, bg + (size_t)layer * SQ, gatep);
        scan_kernel<<<BQ * SQ, SCAN_T>>>(gatep, comb, ostates + layer * BQ * SQ);
        {
            dim3 grid((DQ + BN - 1) / BN, MROWS / BM);
            sgemm_bias<<<grid, 256>>>(comb, Wo + (size_t)layer * DSQ * DQ,
                                      bo + (size_t)layer * DQ, nxt,
                                      MROWS, DQ, DSQ);
        }
        float* t = cur; cur = nxt; nxt = t;
    }

    // 3) layernorm
    layernorm_kernel<<<(MROWS * 32 + 255) / 256, 256>>>(cur, gamma, beta, hn);

    // 4) hn -> fp16
    to_half_kernel<<<(MROWS * DQ + 255) / 256, 256>>>(hn, Af, MROWS * DQ);

    // 5) logits via fp16 HMMA tensor cores (4096x256 @ 256x32000)
    {
        dim3 grid(VOCABQ / TCN, MROWS / TCM);   // 250 x 32
        hgemm_logits<<<grid, 256>>>(Af, Bt, bc, logits);
    }

    // 6) recon = hn @ Wr + br (fp32)
    {
        dim3 grid(DQ / BN, MROWS / BM);
        sgemm_bias<<<grid, 256>>>(hn, Wr, br, recon, MROWS, DQ, DQ);
    }
}

// round 7
// speedup vs baseline: 3.9765x; 1.8373x over previous
#include <cuda_runtime.h>
#include <cuda_fp16.h>
#include <cuda_bf16.h>
#include <math.h>
#include <stdint.h>

// ---------------- problem constants ----------------
#define BQ 2
#define LQ 2048
#define MROWS (BQ * LQ)     // 4096
#define DQ 256
#define SQ 8
#define DEPTHQ 4
#define DSQ (DQ + SQ)       // 264
#define NEXT 272            // 264 + 8 gate cols
#define KPAD 288            // padded K for layer GEMMs
#define VOCABQ 32000

typedef __nv_bfloat16 bf16;
typedef __nv_bfloat162 bf162;

// ---------------- scratch (no allocations; zero-init pads load-bearing) ----
__device__ __align__(256) bf16 g_Xh[MROWS * KPAD];
__device__ __align__(256) bf16 g_Xl[MROWS * KPAD];
__device__ __align__(256) bf16 g_Yh[MROWS * KPAD];
__device__ __align__(256) bf16 g_Yl[MROWS * KPAD];
__device__ __align__(256) bf16 g_Ch[MROWS * KPAD];
__device__ __align__(256) bf16 g_Cl[MROWS * KPAD];
__device__ float g_state[MROWS * SQ];
__device__ float g_gatebuf[MROWS * SQ];
__device__ __align__(256) bf16 g_Wieh[DEPTHQ * NEXT * KPAD];
__device__ __align__(256) bf16 g_Wiel[DEPTHQ * NEXT * KPAD];
__device__ __align__(256) bf16 g_Woth[DEPTHQ * DQ * KPAD];
__device__ __align__(256) bf16 g_Wotl[DEPTHQ * DQ * KPAD];
__device__ float g_bie[DEPTHQ * NEXT];
__device__ __align__(256) __half g_Af[MROWS * DQ];
__device__ __align__(256) __half g_Bt[(size_t)VOCABQ * DQ];
__device__ __align__(256) __half g_Wrt[DQ * DQ];

// ================= PTX helpers (base sm_103 ISA only) =================
__device__ __forceinline__ uint32_t smem_u32(const void* p) {
    uint32_t a;
    asm("{ .reg .u64 t; cvta.to.shared.u64 t, %1; cvt.u32.u64 %0, t; }" : "=r"(a) : "l"(p));
    return a;
}
__device__ __forceinline__ void cpa16(uint32_t dst, const void* src) {
    asm volatile("cp.async.cg.shared.global [%0], [%1], 16;" :: "r"(dst), "l"(src));
}
__device__ __forceinline__ void cpa_commit() { asm volatile("cp.async.commit_group;" ::: "memory"); }
__device__ __forceinline__ void cpa_wait1()  { asm volatile("cp.async.wait_group 1;" ::: "memory"); }
__device__ __forceinline__ void cpa_wait0()  { asm volatile("cp.async.wait_group 0;" ::: "memory"); }

__device__ __forceinline__ void ldmx4(uint32_t* r, uint32_t addr) {
    asm volatile("ldmatrix.sync.aligned.m8n8.x4.shared.b16 {%0,%1,%2,%3}, [%4];"
                 : "=r"(r[0]), "=r"(r[1]), "=r"(r[2]), "=r"(r[3]) : "r"(addr));
}
__device__ __forceinline__ void mma16816(float* d, const uint32_t* a, uint32_t b0, uint32_t b1) {
    asm volatile(
        "mma.sync.aligned.m16n8k16.row.col.f32.f16.f16.f32 "
        "{%0,%1,%2,%3}, {%4,%5,%6,%7}, {%8,%9}, {%0,%1,%2,%3};"
        : "+f"(d[0]), "+f"(d[1]), "+f"(d[2]), "+f"(d[3])
        : "r"(a[0]), "r"(a[1]), "r"(a[2]), "r"(a[3]), "r"(b0), "r"(b1));
}
__device__ __forceinline__ void mma16816bf(float* d, const uint32_t* a, uint32_t b0, uint32_t b1) {
    asm volatile(
        "mma.sync.aligned.m16n8k16.row.col.f32.bf16.bf16.f32 "
        "{%0,%1,%2,%3}, {%4,%5,%6,%7}, {%8,%9}, {%0,%1,%2,%3};"
        : "+f"(d[0]), "+f"(d[1]), "+f"(d[2]), "+f"(d[3])
        : "r"(a[0]), "r"(a[1]), "r"(a[2]), "r"(a[3]), "r"(b0), "r"(b1));
}
__device__ __forceinline__ void splitbf(float v, bf16& h, bf16& l) {
    h = __float2bfloat16_rn(v);
    l = __float2bfloat16_rn(v - __bfloat162float(h));
}

// ================= fp16 single-operand GEMM (logits / recon) =================
// C[M, N] = A[M][256] * Bt[N][256]^T + bias.  CTA 128x128, 8 warps (2x4), warp 64x32.
#define TCM 128
#define TCN 128

__global__ __launch_bounds__(256)
void hgemm_f16(const __half* __restrict__ A, const __half* __restrict__ Bt,
               const float* __restrict__ bias, float* __restrict__ C, int ldc) {
    __shared__ __half As[2][TCM * 40];
    __shared__ __half Bs[2][TCN * 40];

    const int tid = threadIdx.x;
    const int wid = tid >> 5, lane = tid & 31;
    const int wm = wid & 1, wn = wid >> 1;
    const int m0 = blockIdx.y * TCM;
    const int n0 = blockIdx.x * TCN;

    float acc[4][4][4];
#pragma unroll
    for (int i = 0; i < 4; i++)
#pragma unroll
        for (int j = 0; j < 4; j++)
#pragma unroll
            for (int q = 0; q < 4; q++) acc[i][j][q] = 0.f;

    const uint32_t asb[2] = { smem_u32(As[0]), smem_u32(As[1]) };
    const uint32_t bsb[2] = { smem_u32(Bs[0]), smem_u32(Bs[1]) };

    auto load_stage = [&](int s, int k0) {
#pragma unroll
        for (int it = 0; it < 2; it++) {
            int i = tid + it * 256;
            int r = i >> 2, c = i & 3;
            cpa16(asb[s] + r * 80 + c * 16, A + (size_t)(m0 + r) * DQ + k0 + c * 8);
        }
#pragma unroll
        for (int it = 0; it < 2; it++) {
            int i = tid + it * 256;
            int r = i >> 2, c = i & 3;
            cpa16(bsb[s] + r * 80 + c * 16, Bt + (size_t)(n0 + r) * DQ + k0 + c * 8);
        }
        cpa_commit();
    };

    load_stage(0, 0);
    const int lrow = lane & 15;
    const int lhalf = lane >> 4;

    for (int kt = 0; kt < 8; kt++) {
        const int cur = kt & 1;
        if (kt < 7) { load_stage(cur ^ 1, (kt + 1) * 32); cpa_wait1(); }
        else        { cpa_wait0(); }
        __syncthreads();

#pragma unroll
        for (int ks = 0; ks < 2; ks++) {
            const int chunk = ks * 2 + lhalf;
            uint32_t af[4][4], bf[2][4];
#pragma unroll
            for (int mi = 0; mi < 4; mi++)
                ldmx4(af[mi], asb[cur] + (wm * 64 + mi * 16 + lrow) * 80 + chunk * 16);
#pragma unroll
            for (int bj = 0; bj < 2; bj++)
                ldmx4(bf[bj], bsb[cur] + (wn * 32 + bj * 16 + lrow) * 80 + chunk * 16);
#pragma unroll
            for (int mi = 0; mi < 4; mi++)
#pragma unroll
                for (int nj = 0; nj < 4; nj++) {
                    int bj = nj >> 1, hi = nj & 1;
                    mma16816(acc[mi][nj], af[mi], bf[bj][hi], bf[bj][hi + 2]);
                }
        }
        __syncthreads();
    }

    const int g = lane >> 2, tig = lane & 3;
#pragma unroll
    for (int mi = 0; mi < 4; mi++) {
#pragma unroll
        for (int nj = 0; nj < 4; nj++) {
            int col = n0 + wn * 32 + nj * 8 + 2 * tig;
            float bx = __ldg(bias + col), by = __ldg(bias + col + 1);
            int row0 = m0 + wm * 64 + mi * 16 + g;
            *(float2*)(C + (size_t)row0 * ldc + col) =
                make_float2(acc[mi][nj][0] + bx, acc[mi][nj][1] + by);
            *(float2*)(C + (size_t)(row0 + 8) * ldc + col) =
                make_float2(acc[mi][nj][2] + bx, acc[mi][nj][3] + by);
        }
    }
}

// ================= bf16-split GEMM for layer GEMMs =================
// C = (Ah+Al)[M][288] * (Bh+Bl)[N][288]^T + bias  (3-term compensated)
// CTA 64x128, 4 warps, warp 64x32, K = 288 (9 chunks of 32).
#define LTM 64
#define LTN 128
#define SAH 0
#define SAL (64 * 40)
#define SBH (2 * 64 * 40)
#define SBL (2 * 64 * 40 + 128 * 40)
#define STG (2 * 64 * 40 + 2 * 128 * 40)   // bf16 elems per stage (15360)
#define SPLIT_SMEM (2 * STG * 2)           // bytes = 61440

__global__ __launch_bounds__(128)
void hgemm_split(const bf16* __restrict__ Ah, const bf16* __restrict__ Al,
                 const bf16* __restrict__ Bh, const bf16* __restrict__ Bl,
                 int nrowsB, const float* __restrict__ bias, int nbias, int mode,
                 bf16* __restrict__ outh, bf16* __restrict__ outl,
                 float* __restrict__ statep, float* __restrict__ gatep) {
    extern __shared__ bf16 sm[];
    const int tid = threadIdx.x;
    const int wn = tid >> 5, lane = tid & 31;
    const int m0 = blockIdx.y * LTM;
    const int n0 = blockIdx.x * LTN;

    float acc[4][4][4];
#pragma unroll
    for (int i = 0; i < 4; i++)
#pragma unroll
        for (int j = 0; j < 4; j++)
#pragma unroll
            for (int q = 0; q < 4; q++) acc[i][j][q] = 0.f;

    const uint32_t sb0 = smem_u32(sm);

    auto load_stage = [&](int s, int k0) {
        const uint32_t sb = sb0 + s * STG * 2;
#pragma unroll
        for (int it = 0; it < 2; it++) {
            int i = tid + it * 128;                 // 0..255: A rows 64 x 4 chunks
            int r = i >> 2, c = i & 3;
            size_t goff = (size_t)(m0 + r) * KPAD + k0 + c * 8;
            cpa16(sb + (SAH + r * 40) * 2 + c * 16, Ah + goff);
            cpa16(sb + (SAL + r * 40) * 2 + c * 16, Al + goff);
        }
#pragma unroll
        for (int it = 0; it < 4; it++) {
            int i = tid + it * 128;                 // 0..511: B rows 128 x 4 chunks
            int r = i >> 2, c = i & 3;
            int rr = n0 + r; if (rr >= nrowsB) rr = 0;
            size_t goff = (size_t)rr * KPAD + k0 + c * 8;
            cpa16(sb + (SBH + r * 40) * 2 + c * 16, Bh + goff);
            cpa16(sb + (SBL + r * 40) * 2 + c * 16, Bl + goff);
        }
        cpa_commit();
    };

    load_stage(0, 0);
    const int lrow = lane & 15;
    const int lhalf = lane >> 4;

    for (int kt = 0; kt < KPAD / 32; kt++) {        // 9 chunks
        const int cur = kt & 1;
        if (kt < KPAD / 32 - 1) { load_stage(cur ^ 1, (kt + 1) * 32); cpa_wait1(); }
        else                    { cpa_wait0(); }
        __syncthreads();
        const uint32_t sb = sb0 + cur * STG * 2;

#pragma unroll
        for (int ks = 0; ks < 2; ks++) {
            const int chunk = ks * 2 + lhalf;
            uint32_t afh[4][4], afl[4][4], bfh[2][4], bfl[2][4];
#pragma unroll
            for (int mi = 0; mi < 4; mi++) {
                int r = mi * 16 + lrow;
                ldmx4(afh[mi], sb + (SAH + r * 40) * 2 + chunk * 16);
                ldmx4(afl[mi], sb + (SAL + r * 40) * 2 + chunk * 16);
            }
#pragma unroll
            for (int bj = 0; bj < 2; bj++) {
                int r = wn * 32 + bj * 16 + lrow;
                ldmx4(bfh[bj], sb + (SBH + r * 40) * 2 + chunk * 16);
                ldmx4(bfl[bj], sb + (SBL + r * 40) * 2 + chunk * 16);
            }
#pragma unroll
            for (int mi = 0; mi < 4; mi++)
#pragma unroll
                for (int nj = 0; nj < 4; nj++) {
                    int bj = nj >> 1, hi = nj & 1;
                    mma16816bf(acc[mi][nj], afh[mi], bfh[bj][hi], bfh[bj][hi + 2]);
                    mma16816bf(acc[mi][nj], afl[mi], bfh[bj][hi], bfh[bj][hi + 2]);
                    mma16816bf(acc[mi][nj], afh[mi], bfl[bj][hi], bfl[bj][hi + 2]);
                }
        }
        __syncthreads();
    }

    // epilogue
    const int g = lane >> 2, tig = lane & 3;
#pragma unroll
    for (int mi = 0; mi < 4; mi++) {
#pragma unroll
        for (int nj = 0; nj < 4; nj++) {
            int col = n0 + wn * 32 + nj * 8 + 2 * tig;
            if (col >= nbias) continue;
            float bx = __ldg(bias + col), by = __ldg(bias + col + 1);
            int r0 = m0 + mi * 16 + g;
#pragma unroll
            for (int half = 0; half < 2; half++) {
                int r = r0 + half * 8;
                float v0 = acc[mi][nj][half * 2 + 0] + bx;
                float v1 = acc[mi][nj][half * 2 + 1] + by;
                if (mode == 0 || col < 256) {
                    bf16 h0, l0, h1, l1;
                    splitbf(v0, h0, l0); splitbf(v1, h1, l1);
                    *(bf162*)(outh + (size_t)r * KPAD + col) = __halves2bfloat162(h0, h1);
                    *(bf162*)(outl + (size_t)r * KPAD + col) = __halves2bfloat162(l0, l1);
                } else if (col < 264) {
                    *(float2*)(statep + r * SQ + (col - 256)) = make_float2(v0, v1);
                } else {  // 264..271
                    gatep[r * SQ + (col - 264)]     = 1.f / (1.f + expf(-v0));
                    gatep[r * SQ + (col - 264) + 1] = 1.f / (1.f + expf(-v1));
                }
            }
        }
    }
}

// ================= weight prep kernels =================
// Wie^T split: [l][n][k], n<272, k<256.  n>=264 -> folded Wi*Wg.  Also bie.
__global__ void prep_wie(const float* __restrict__ Wi, const float* __restrict__ Wg,
                         const float* __restrict__ bi, const float* __restrict__ bg,
                         bf16* __restrict__ Wh, bf16* __restrict__ Wl,
                         float* __restrict__ bie) {
    int n = blockIdx.x, l = blockIdx.y, k = threadIdx.x;   // k in 0..255
    const float* Wil = Wi + (size_t)l * DQ * DSQ;
    const float* Wgl = Wg + (size_t)l * DSQ * SQ;
    float w;
    if (n < DSQ) {
        w = Wil[k * DSQ + n];
    } else {
        int s = n - DSQ;
        float a = 0.f;
        for (int e = 0; e < DSQ; e++) a += Wil[k * DSQ + e] * Wgl[e * SQ + s];
        w = a;
    }
    bf16 h, lo; splitbf(w, h, lo);
    size_t o = ((size_t)l * NEXT + n) * KPAD + k;
    Wh[o] = h; Wl[o] = lo;
    if (k == 0) {
        float b;
        if (n < DSQ) b = bi[l * DSQ + n];
        else {
            int s = n - DSQ;
            float a = bg[l * SQ + s];
            for (int e = 0; e < DSQ; e++) a += bi[l * DSQ + e] * Wgl[e * SQ + s];
            b = a;
        }
        bie[l * NEXT + n] = b;
    }
}

// Wo^T split: Wot[l][d][e] = Wo[l][e][d], d<256, e<264
__global__ void prep_wot(const float* __restrict__ Wo,
                         bf16* __restrict__ Wh, bf16* __restrict__ Wl) {
    int e = blockIdx.x, l = blockIdx.y, d = threadIdx.x;
    float w = Wo[((size_t)l * DSQ + e) * DQ + d];
    bf16 h, lo; splitbf(w, h, lo);
    size_t o = ((size_t)l * DQ + d) * KPAD + e;
    Wh[o] = h; Wl[o] = lo;
}

// generic [256][ncols] f32 -> [ncols][256] fp16 transpose
__global__ __launch_bounds__(256)
void transpose_f32_to_f16(const float* __restrict__ src, __half* __restrict__ dst, int ncols) {
    __shared__ float t[32][33];
    const int n0 = blockIdx.x * 32;
    const int k0 = blockIdx.y * 32;
    const int tx = threadIdx.x, ty = threadIdx.y;   // 32 x 8
#pragma unroll
    for (int r = 0; r < 4; r++)
        t[ty * 4 + r][tx] = src[(size_t)(k0 + ty * 4 + r) * ncols + n0 + tx];
    __syncthreads();
#pragma unroll
    for (int r = 0; r < 4; r++)
        dst[(size_t)(n0 + ty * 4 + r) * DQ + k0 + tx] = __float2half_rn(t[tx][ty * 4 + r]);
}

// ---------------- embed gather -> split bf16 ----------------
__global__ void embed_kernel(const int* __restrict__ x_t,
                             const float* __restrict__ table,
                             bf16* __restrict__ hh, bf16* __restrict__ hl) {
    int i = blockIdx.x * blockDim.x + threadIdx.x;   // over MROWS*128
    if (i >= MROWS * 128) return;
    int row = i >> 7;
    int d0 = (i & 127) * 2;
    const float* tr = table + (size_t)x_t[row] * DQ + d0;
    float v0 = tr[0], v1 = tr[1];
    bf16 h0, l0, h1, l1;
    splitbf(v0, h0, l0); splitbf(v1, h1, l1);
    *(bf162*)(hh + (size_t)row * KPAD + d0) = __halves2bfloat162(h0, h1);
    *(bf162*)(hl + (size_t)row * KPAD + d0) = __halves2bfloat162(l0, l1);
}

// ---------------- parallel scan over L ----------------
#define SCAN_T 256
#define SCAN_STEPS (LQ / SCAN_T)   // 8

__global__ __launch_bounds__(SCAN_T)
void scan_kernel(const float* __restrict__ gate,
                 const float* __restrict__ state_in,
                 bf16* __restrict__ combh, bf16* __restrict__ combl,
                 float* __restrict__ out_states) {
    const int b = blockIdx.x >> 3;
    const int s = blockIdx.x & 7;
    const int t = threadIdx.x;
    const int l0 = t * SCAN_STEPS;

    float g[SCAN_STEPS], si[SCAN_STEPS];
#pragma unroll
    for (int u = 0; u < SCAN_STEPS; u++) {
        int idx = b * LQ + l0 + u;
        g[u]  = gate[idx * SQ + s];
        si[u] = state_in[idx * SQ + s];
    }

    float a = 1.f, bb = 0.f;
#pragma unroll
    for (int u = 0; u < SCAN_STEPS; u++) {
        a  = g[u] * a;
        bb = g[u] * bb + (1.f - g[u]) * si[u];
    }

    __shared__ float sa[SCAN_T], sbv[SCAN_T];
    sa[t] = a; sbv[t] = bb;
    __syncthreads();

#pragma unroll
    for (int off = 1; off < SCAN_T; off <<= 1) {
        float pa = 1.f, pb = 0.f, ca = sa[t], cb = sbv[t];
        if (t >= off) { pa = sa[t - off]; pb = sbv[t - off]; }
        __syncthreads();
        if (t >= off) { sa[t] = ca * pa; sbv[t] = ca * pb + cb; }
        __syncthreads();
    }

    float st = (t == 0) ? 0.f : sbv[t - 1];
#pragma unroll
    for (int u = 0; u < SCAN_STEPS; u++) {
        int idx = b * LQ + l0 + u;
        st = g[u] * st + (1.f - g[u]) * si[u];
        bf16 h, lo; splitbf(st, h, lo);
        combh[(size_t)idx * KPAD + DQ + s] = h;
        combl[(size_t)idx * KPAD + DQ + s] = lo;
    }
    if (t == SCAN_T - 1) out_states[b * SQ + s] = st;
}

// ---------------- layernorm: (hi+lo) fp32 math -> fp16 out ----------------
__global__ __launch_bounds__(256)
void layernorm_kernel(const bf16* __restrict__ xh, const bf16* __restrict__ xl,
                      const float* __restrict__ gamma, const float* __restrict__ beta,
                      __half* __restrict__ y) {
    int warp = (blockIdx.x * blockDim.x + threadIdx.x) >> 5;
    int lane = threadIdx.x & 31;
    if (warp >= MROWS) return;
    const bf16* xhr = xh + (size_t)warp * KPAD;
    const bf16* xlr = xl + (size_t)warp * KPAD;
    float v[8];
    float sum = 0.f;
#pragma unroll
    for (int i = 0; i < 8; i++) {
        int d = lane + i * 32;
        v[i] = __bfloat162float(xhr[d]) + __bfloat162float(xlr[d]);
        sum += v[i];
    }
#pragma unroll
    for (int o = 16; o; o >>= 1) sum += __shfl_xor_sync(0xFFFFFFFFu, sum, o);
    float mu = sum * (1.f / 256.f);
    float vs = 0.f;
#pragma unroll
    for (int i = 0; i < 8; i++) { float d = v[i] - mu; vs += d * d; }
#pragma unroll
    for (int o = 16; o; o >>= 1) vs += __shfl_xor_sync(0xFFFFFFFFu, vs, o);
    float r = rsqrtf(vs * (1.f / 256.f) + 1e-5f);
    __half* yr = y + (size_t)warp * DQ;
#pragma unroll
    for (int i = 0; i < 8; i++) {
        int d = lane + i * 32;
        yr[d] = __float2half_rn((v[i] - mu) * r * gamma[d] + beta[d]);
    }
}

// ---------------- launch ----------------
extern "C" void kernel_launch(void* const* d_in, const int* in_sizes, int n_in,
                              void* d_out, int out_size) {
    const int*   x_t   = (const int*)  d_in[0];
    const float* table = (const float*)d_in[1];
    const float* Wi    = (const float*)d_in[2];
    const float* bi    = (const float*)d_in[3];
    const float* Wg    = (const float*)d_in[4];
    const float* bg    = (const float*)d_in[5];
    const float* Wo    = (const float*)d_in[6];
    const float* bo    = (const float*)d_in[7];
    const float* gamma = (const float*)d_in[8];
    const float* beta  = (const float*)d_in[9];
    const float* Wc    = (const float*)d_in[10];
    const float* bc    = (const float*)d_in[11];
    const float* Wr    = (const float*)d_in[12];
    const float* br    = (const float*)d_in[13];

    float* out = (float*)d_out;
    const size_t logits_elems = (size_t)MROWS * VOCABQ;
    const size_t recon_elems  = (size_t)MROWS * DQ;
    float* logits  = out;
    float* recon   = out + logits_elems;
    float* ostates = out + logits_elems + recon_elems;

    bf16 *Xh, *Xl, *Yh, *Yl, *Ch, *Cl, *Wieh, *Wiel, *Woth, *Wotl;
    __half *Af, *Bt, *Wrt;
    float *statep, *gatep, *bie;
    cudaGetSymbolAddress((void**)&Xh, g_Xh);   cudaGetSymbolAddress((void**)&Xl, g_Xl);
    cudaGetSymbolAddress((void**)&Yh, g_Yh);   cudaGetSymbolAddress((void**)&Yl, g_Yl);
    cudaGetSymbolAddress((void**)&Ch, g_Ch);   cudaGetSymbolAddress((void**)&Cl, g_Cl);
    cudaGetSymbolAddress((void**)&Wieh, g_Wieh); cudaGetSymbolAddress((void**)&Wiel, g_Wiel);
    cudaGetSymbolAddress((void**)&Woth, g_Woth); cudaGetSymbolAddress((void**)&Wotl, g_Wotl);
    cudaGetSymbolAddress((void**)&Af, g_Af);   cudaGetSymbolAddress((void**)&Bt, g_Bt);
    cudaGetSymbolAddress((void**)&Wrt, g_Wrt);
    cudaGetSymbolAddress((void**)&statep, g_state);
    cudaGetSymbolAddress((void**)&gatep, g_gatebuf);
    cudaGetSymbolAddress((void**)&bie, g_bie);

    cudaFuncSetAttribute(hgemm_split, cudaFuncAttributeMaxDynamicSharedMemorySize, SPLIT_SMEM);

    // ---- weight prep ----
    prep_wie<<<dim3(NEXT, DEPTHQ), 256>>>(Wi, Wg, bi, bg, Wieh, Wiel, bie);
    prep_wot<<<dim3(DSQ, DEPTHQ), 256>>>(Wo, Woth, Wotl);
    transpose_f32_to_f16<<<dim3(VOCABQ / 32, DQ / 32), dim3(32, 8)>>>(Wc, Bt, VOCABQ);
    transpose_f32_to_f16<<<dim3(DQ / 32, DQ / 32), dim3(32, 8)>>>(Wr, Wrt, DQ);

    // ---- embed (split) ----
    embed_kernel<<<(MROWS * 128 + 255) / 256, 256>>>(x_t, table, Xh, Xl);

    // ---- layers ----
    bf16 *curh = Xh, *curl = Xl, *nxth = Yh, *nxtl = Yl;
    for (int layer = 0; layer < DEPTHQ; layer++) {
        // combined-ext GEMM: N=272 (264 comb + 8 gate), mode 1
        {
            dim3 grid((NEXT + LTN - 1) / LTN, MROWS / LTM);   // 3 x 64
            hgemm_split<<<grid, 128, SPLIT_SMEM>>>(
                curh, curl,
                Wieh + (size_t)layer * NEXT * KPAD, Wiel + (size_t)layer * NEXT * KPAD,
                NEXT, bie + layer * NEXT, NEXT, 1,
                Ch, Cl, statep, gatep);
        }
        // scan: states -> comb cols 256..263 (split), finals -> out
        scan_kernel<<<BQ * SQ, SCAN_T>>>(gatep, statep, Ch, Cl,
                                         ostates + layer * BQ * SQ);
        // out GEMM: N=256, mode 0 -> next h (split)
        {
            dim3 grid(DQ / LTN, MROWS / LTM);                 // 2 x 64
            hgemm_split<<<grid, 128, SPLIT_SMEM>>>(
                Ch, Cl,
                Woth + (size_t)layer * DQ * KPAD, Wotl + (size_t)layer * DQ * KPAD,
                DQ, bo + layer * DQ, DQ, 0,
                nxth, nxtl, nullptr, nullptr);
        }
        bf16* t;
        t = curh; curh = nxth; nxth = t;
        t = curl; curl = nxtl; nxtl = t;
    }

    // ---- layernorm -> fp16 ----
    layernorm_kernel<<<(MROWS * 32 + 255) / 256, 256>>>(curh, curl, gamma, beta, Af);

    // ---- logits (fp16 HMMA) ----
    {
        dim3 grid(VOCABQ / TCN, MROWS / TCM);   // 250 x 32
        hgemm_f16<<<grid, 256>>>(Af, Bt, bc, logits, VOCABQ);
    }
    // ---- recon (fp16 HMMA) ----
    {
        dim3 grid(DQ / TCN, MROWS / TCM);       // 2 x 32
        hgemm_f16<<<grid, 256>>>(Af, Wrt, br, recon, DQ);
    }
}